// round 16
// baseline (speedup 1.0000x reference)
#include <cuda_runtime.h>
#include <cuda_bf16.h>
#include <cuda_fp16.h>
#include <cstdint>
#include <math.h>

// ---------------- problem constants ----------------
#define HH   16        // H
#define HKV  8
#define DD   128       // D
#define TT   2048      // T
#define HID  2048
#define II   8192      // I
#define NREP 2
#define EPSF 1e-6f
#define SCALEF 0.08838834764831845f   // 1/sqrt(128)

// ---------------- scratch (device globals, no allocs) ----------------
__device__ float g_x  [TT * HID];
__device__ float g_hid[TT * HID];
// fp16 activation buffers
__device__ __align__(16) __half g_h_h  [TT * HID];
__device__ __align__(16) __half g_att_h[TT * HH * DD];
__device__ __align__(16) __half g_h2_h [TT * HID];
__device__ __align__(16) __half g_act_h[TT * II];
__device__ __align__(16) __half g_q_h  [TT * HH * DD];   // raw qkv -> rope in place
__device__ __align__(16) __half g_k_h  [TT * HKV * DD];
__device__ __align__(16) __half g_v_h  [TT * HKV * DD];
__device__ __align__(16) __half g_vt_h [HKV * DD * TT];  // [hk][d][t]
// fp16 weights (converted every replay)
__device__ __align__(16) __half g_wqkv_h[4096 * HID];
__device__ __align__(16) __half g_wgu_h [2 * II * HID];  // gate/up row-interleaved
__device__ __align__(16) __half g_wo_h  [HID * HH * DD];
__device__ __align__(16) __half g_wd_h  [HID * II];

// ---------------- fp32 -> fp16 conversion (8 floats / thread) ----------------
__device__ __forceinline__ uint4 cvt8(float4 a, float4 b) {
    __half2 h0 = __floats2half2_rn(a.x, a.y);
    __half2 h1 = __floats2half2_rn(a.z, a.w);
    __half2 h2 = __floats2half2_rn(b.x, b.y);
    __half2 h3 = __floats2half2_rn(b.z, b.w);
    return make_uint4(*(uint32_t*)&h0, *(uint32_t*)&h1,
                      *(uint32_t*)&h2, *(uint32_t*)&h3);
}

__global__ void cvt_f16(const float4* __restrict__ src, uint4* __restrict__ dst, int n8) {
    int i = blockIdx.x * blockDim.x + threadIdx.x;
    if (i < n8) {
        float4 a = src[2 * i], b = src[2 * i + 1];
        dst[i] = cvt8(a, b);
    }
}

// fused wq/wk/wv conversion (same 8-float/thread pattern, one launch)
__global__ void cvt_f16_qkv(const float4* __restrict__ wq, const float4* __restrict__ wk,
                            const float4* __restrict__ wv, uint4* __restrict__ dst) {
    int i = blockIdx.x * blockDim.x + threadIdx.x;   // 1048576 threads
    const float4* s;
    uint4* d;
    if (i < 524288)      { s = wq + 2 * i;                     d = dst + i; }
    else if (i < 786432) { int j = i - 524288; s = wk + 2 * j; d = dst + 524288 + j; }
    else                 { int j = i - 786432; s = wv + 2 * j; d = dst + 786432 + j; }
    float4 a = s[0], b = s[1];
    d[0] = cvt8(a, b);
}

// wgu conversion with gate/up row interleave: dst row 2j = gate_j, 2j+1 = up_j.
__global__ void cvt_f16_gu(const float4* __restrict__ src, uint4* __restrict__ dst) {
    int i = blockIdx.x * blockDim.x + threadIdx.x;   // over 16384*256
    int row = i >> 8, chunk = i & 255;
    int drow = (row < II) ? (row << 1) : (((row - II) << 1) | 1);
    float4 a = src[2 * i], b = src[2 * i + 1];
    dst[drow * 256 + chunk] = cvt8(a, b);
}

// ---------------- transpose: src[R][C] -> dst[C][R] (fp32) ----------------
__global__ void transpose_k(const float* __restrict__ src, float* __restrict__ dst,
                            int R, int C) {
    __shared__ float tile[32][33];
    int r0 = blockIdx.y * 32, c0 = blockIdx.x * 32;
    int tx = threadIdx.x, ty = threadIdx.y;
    #pragma unroll
    for (int i = ty; i < 32; i += 8)
        tile[i][tx] = src[(size_t)(r0 + i) * C + c0 + tx];
    __syncthreads();
    #pragma unroll
    for (int i = ty; i < 32; i += 8)
        dst[(size_t)(c0 + i) * R + r0 + tx] = tile[tx][i];
}

// ---------------- V transpose: [T][HKV][D] f16 -> [hk][d][t] f16 -----
__global__ void v_trans_h2(const __half* __restrict__ V, __half* __restrict__ VT) {
    __shared__ __half tile[32][33];
    int t0 = blockIdx.x * 32, d0 = blockIdx.y * 32, hk = blockIdx.z;
    int tx = threadIdx.x, ty = threadIdx.y;
    #pragma unroll
    for (int i = ty; i < 32; i += 8)
        tile[i][tx] = V[((size_t)(t0 + i) * HKV + hk) * DD + d0 + tx];
    __syncthreads();
    #pragma unroll
    for (int i = ty; i < 32; i += 8)
        VT[((size_t)hk * DD + d0 + i) * TT + t0 + tx] = tile[tx][i];
}

// ---------------- row RMS norm, fp16 output ----------------
__global__ void rms_rows_h(const float* __restrict__ X, const float* __restrict__ w,
                           __half* __restrict__ Y, int C) {
    int t = blockIdx.x;
    const float4* x4 = (const float4*)(X + (size_t)t * C);
    const float4* w4 = (const float4*)w;
    __half2*      y2 = (__half2*)(Y + (size_t)t * C);
    int n4 = C >> 2;
    float4 v[4];
    float ss = 0.f;
    int cnt = 0;
    for (int i = threadIdx.x; i < n4; i += 256) {
        float4 a = x4[i];
        v[cnt++] = a;
        ss += a.x * a.x + a.y * a.y + a.z * a.z + a.w * a.w;
    }
    #pragma unroll
    for (int o = 16; o; o >>= 1) ss += __shfl_xor_sync(0xffffffffu, ss, o);
    __shared__ float warpsum[8];
    if ((threadIdx.x & 31) == 0) warpsum[threadIdx.x >> 5] = ss;
    __syncthreads();
    ss = 0.f;
    #pragma unroll
    for (int i = 0; i < 8; i++) ss += warpsum[i];
    float r = rsqrtf(ss / (float)C + EPSF);
    cnt = 0;
    for (int i = threadIdx.x; i < n4; i += 256) {
        float4 a = v[cnt++];
        float4 ww = w4[i];
        y2[2 * i]     = __floats2half2_rn(a.x * r * ww.x, a.y * r * ww.y);
        y2[2 * i + 1] = __floats2half2_rn(a.z * r * ww.z, a.w * r * ww.w);
    }
}

// ---------------- per-head RMS + RoPE, fp16 in-place ----------------
__global__ void qk_rms_rope_h2(__half* __restrict__ buf, const float* __restrict__ w,
                               const float* __restrict__ cosT, const float* __restrict__ sinT,
                               float scale) {
    int h = blockIdx.x, t = blockIdx.y, nh = gridDim.x;
    __half* row = buf + ((size_t)t * nh + h) * DD;
    int d = threadIdx.x;
    float v = __half2float(row[d]);
    float ss = v * v;
    #pragma unroll
    for (int o = 16; o; o >>= 1) ss += __shfl_xor_sync(0xffffffffu, ss, o);
    __shared__ float wsum[4];
    if ((d & 31) == 0) wsum[d >> 5] = ss;
    __syncthreads();
    ss = wsum[0] + wsum[1] + wsum[2] + wsum[3];
    float r = rsqrtf(ss / 128.f + EPSF);
    float qn = v * r * w[d];
    __shared__ float sh[128];
    sh[d] = qn;
    __syncthreads();
    float rot = (d < 64) ? -sh[d + 64] : sh[d - 64];
    float val = (qn * cosT[(size_t)t * DD + d] + rot * sinT[(size_t)t * DD + d]) * scale;
    row[d] = __float2half(val);
}

#define MMA_F16(d, a, b)                                                      \
    asm volatile("mma.sync.aligned.m16n8k16.row.col.f32.f16.f16.f32 "         \
                 "{%0,%1,%2,%3}, {%4,%5,%6,%7}, {%8,%9}, {%0,%1,%2,%3};"      \
                 : "+f"(d[0]), "+f"(d[1]), "+f"(d[2]), "+f"(d[3])             \
                 : "r"(a[0]), "r"(a[1]), "r"(a[2]), "r"(a[3]),                \
                   "r"(b[0]), "r"(b[1]))

#define LDSM_X4(r0, r1, r2, r3, addr)                                         \
    asm volatile("ldmatrix.sync.aligned.m8n8.x4.shared.b16 {%0,%1,%2,%3}, [%4];" \
                 : "=r"(r0), "=r"(r1), "=r"(r2), "=r"(r3) : "r"(addr))

#define CP_ASYNC16(dst, src)                                                  \
    asm volatile("cp.async.cg.shared.global [%0], [%1], 16;\n"                \
                 :: "r"(dst), "l"(src))

// ---------------- fp16 tensor-core GEMM, cp.async 3-stage, BK=64, ldmatrix ---
// C[M,N] = A[M,K] * B[N,K]^T.  BN template: 128 (warp 64x32) or 256 (warp 64x64).
// MODE 0: +Res, fp32 out.  MODE 1: QKV routing, fp16 out.
// MODE 2: gate/up interleaved -> fused silu, fp16 out [M][N/2].
// MODE 3: +Res, fp32 out TRANSPOSED via smem staging ([N][T] layout).
#define HPITCH 72    // halfs per smem row (144 B): ldmatrix 8-row phase conflict-free
#define SMEM_G(BN) (3 * (128 + (BN)) * HPITCH * 2)   // 110592 B / 165888 B

template<int MODE, int BN, int MINB>
__global__ __launch_bounds__(256, MINB) void gemm_f16(
    const __half* __restrict__ A, const __half* __restrict__ B,
    const float* __restrict__ Res, float* __restrict__ C,
    __half* __restrict__ H0, __half* __restrict__ H1, __half* __restrict__ H2,
    int N, int K) {
    constexpr int BM = 128;
    constexpr int WN = BN / 4;      // warp n-tile
    constexpr int NF = WN / 8;      // b-fragments per warp (4 or 8)
    extern __shared__ __half shm[];
    __half* SA = shm;                     // [3][BM][HPITCH]
    __half* SB = shm + 3 * BM * HPITCH;   // [3][BN][HPITCH]

    const int bm = blockIdx.y * BM;
    const int bn = blockIdx.x * BN;
    const int tid = threadIdx.x;
    const int wid = tid >> 5, lane = tid & 31;
    const int wm = wid & 1, wn = wid >> 1;
    const int lr = lane >> 2, lc = lane & 3;
    const int nkt = K >> 6;

    // ldmatrix lane-address components
    const int amat = lane >> 3;
    const int arow = ((amat & 1) << 3) + (lane & 7);
    const int acol = (amat >> 1) << 3;
    const int brow = ((amat >> 1) << 3) + (lane & 7);
    const int bcol = (amat & 1) << 3;
    const uint32_t sa0 = (uint32_t)__cvta_generic_to_shared(SA);
    const uint32_t sb0 = (uint32_t)__cvta_generic_to_shared(SB);
    const uint32_t a_off = sa0 + ((wm * 64 + arow) * HPITCH + acol) * 2;
    const uint32_t b_off = sb0 + ((wn * WN + brow) * HPITCH + bcol) * 2;

    auto issue = [&](int kt, int s) {
        int k0 = kt << 6;
        #pragma unroll
        for (int i = 0; i < 4; i++) {
            int cid = tid + i * 256;
            int r = cid >> 3, ch = cid & 7;          // 8 x 16B chunks per 128B row
            const __half* g = A + (size_t)(bm + r) * K + k0 + ch * 8;
            uint32_t dst = (uint32_t)__cvta_generic_to_shared(
                &SA[(s * BM + r) * HPITCH + ch * 8]);
            CP_ASYNC16(dst, g);
        }
        #pragma unroll
        for (int i = 0; i < BN / 32; i++) {
            int cid = tid + i * 256;
            int r = cid >> 3, ch = cid & 7;
            const __half* g = B + (size_t)(bn + r) * K + k0 + ch * 8;
            uint32_t dst = (uint32_t)__cvta_generic_to_shared(
                &SB[(s * BN + r) * HPITCH + ch * 8]);
            CP_ASYNC16(dst, g);
        }
        asm volatile("cp.async.commit_group;\n");
    };

    float acc[4][NF][4] = {};

    issue(0, 0);
    issue(1, 1);

    for (int kt = 0; kt < nkt; kt++) {
        int s = kt % 3;
        if (kt == nkt - 1) { asm volatile("cp.async.wait_group 0;\n"); }
        else               { asm volatile("cp.async.wait_group 1;\n"); }
        __syncthreads();
        if (kt + 2 < nkt) issue(kt + 2, (kt + 2) % 3);

        uint32_t abase = a_off + s * (BM * HPITCH * 2);
        uint32_t bbase = b_off + s * (BN * HPITCH * 2);
        #pragma unroll
        for (int ks = 0; ks < 64; ks += 16) {
            uint32_t af[4][4], bf[NF][2];
            #pragma unroll
            for (int mf = 0; mf < 4; mf++)
                LDSM_X4(af[mf][0], af[mf][1], af[mf][2], af[mf][3],
                        abase + (mf * 16 * HPITCH + ks) * 2);
            #pragma unroll
            for (int t = 0; t < NF / 2; t++)
                LDSM_X4(bf[2 * t][0], bf[2 * t][1], bf[2 * t + 1][0], bf[2 * t + 1][1],
                        bbase + (t * 16 * HPITCH + ks) * 2);
            #pragma unroll
            for (int mf = 0; mf < 4; mf++)
                #pragma unroll
                for (int nf = 0; nf < NF; nf++)
                    MMA_F16(acc[mf][nf], af[mf], bf[nf]);
        }
    }

    if (MODE == 1) {
        // fp16 QKV routing
        __half* Cb;
        int Nloc, cl0;
        if (bn < 2048)      { Cb = H0; Nloc = 2048; cl0 = bn; }
        else if (bn < 3072) { Cb = H1; Nloc = 1024; cl0 = bn - 2048; }
        else                { Cb = H2; Nloc = 1024; cl0 = bn - 3072; }
        #pragma unroll
        for (int mf = 0; mf < 4; mf++) {
            #pragma unroll
            for (int nf = 0; nf < NF; nf++) {
                int rg = bm + wm * 64 + mf * 16 + lr;
                int cg = cl0 + wn * WN + nf * 8 + 2 * lc;
                __half2 v0 = __floats2half2_rn(acc[mf][nf][0], acc[mf][nf][1]);
                __half2 v1 = __floats2half2_rn(acc[mf][nf][2], acc[mf][nf][3]);
                *(__half2*)(Cb + (size_t)rg * Nloc + cg) = v0;
                *(__half2*)(Cb + (size_t)(rg + 8) * Nloc + cg) = v1;
            }
        }
        return;
    }
    if (MODE == 2) {
        #pragma unroll
        for (int mf = 0; mf < 4; mf++) {
            #pragma unroll
            for (int nf = 0; nf < NF; nf++) {
                int rg = bm + wm * 64 + mf * 16 + lr;
                int j = ((bn + wn * WN + nf * 8) >> 1) + lc;
                float g0 = acc[mf][nf][0], u0 = acc[mf][nf][1];
                float g1 = acc[mf][nf][2], u1 = acc[mf][nf][3];
                H0[(size_t)rg * (N / 2) + j] =
                    __float2half(g0 / (1.f + __expf(-g0)) * u0);
                H0[(size_t)(rg + 8) * (N / 2) + j] =
                    __float2half(g1 / (1.f + __expf(-g1)) * u1);
            }
        }
        return;
    }
    if (MODE == 3) {
        // residual add, stage through smem (pitch 132), coalesced transposed store
        __syncthreads();
        float* sf = (float*)shm;          // [BN cols][132] floats, fits in SMEM_G(BN)
        #pragma unroll
        for (int mf = 0; mf < 4; mf++) {
            #pragma unroll
            for (int nf = 0; nf < NF; nf++) {
                int rl = wm * 64 + mf * 16 + lr;
                int cl = wn * WN + nf * 8 + 2 * lc;
                int rg = bm + rl;
                float2 r0 = *(const float2*)(Res + (size_t)rg * N + bn + cl);
                float2 r1 = *(const float2*)(Res + (size_t)(rg + 8) * N + bn + cl);
                sf[cl * 132 + rl]           = acc[mf][nf][0] + r0.x;
                sf[(cl + 1) * 132 + rl]     = acc[mf][nf][1] + r0.y;
                sf[cl * 132 + rl + 8]       = acc[mf][nf][2] + r1.x;
                sf[(cl + 1) * 132 + rl + 8] = acc[mf][nf][3] + r1.y;
            }
        }
        __syncthreads();
        #pragma unroll
        for (int i = 0; i < BN / 8; i++) {
            int cl = wid * (BN / 8) + i;
            #pragma unroll
            for (int j = 0; j < 4; j++)
                C[(size_t)(bn + cl) * TT + bm + lane + 32 * j] =
                    sf[cl * 132 + lane + 32 * j];
        }
        return;
    }
    // MODE 0
    #pragma unroll
    for (int mf = 0; mf < 4; mf++) {
        #pragma unroll
        for (int nf = 0; nf < NF; nf++) {
            int rg = bm + wm * 64 + mf * 16 + lr;
            int cg = bn + wn * WN + nf * 8 + 2 * lc;
            float2 v0 = make_float2(acc[mf][nf][0], acc[mf][nf][1]);
            float2 v1 = make_float2(acc[mf][nf][2], acc[mf][nf][3]);
            if (Res) {
                float2 r0 = *(const float2*)(Res + (size_t)rg * N + cg);
                float2 r1 = *(const float2*)(Res + (size_t)(rg + 8) * N + cg);
                v0.x += r0.x; v0.y += r0.y;
                v1.x += r1.x; v1.y += r1.y;
            }
            *(float2*)(C + (size_t)rg * N + cg) = v0;
            *(float2*)(C + (size_t)(rg + 8) * N + cg) = v1;
        }
    }
}

// ---------------- tensor-core flash attention, cp.async double-buffered K/V --
#define ATT_QP 136
#define ATT_KP 136
#define ATT_VP 72
#define ATT_SMEM ((128 * ATT_QP + 2 * (64 * ATT_KP + 128 * ATT_VP)) * 2)  // 106496 B

__global__ __launch_bounds__(256, 1) void flash_attn_h(
    const __half* __restrict__ Qh, const __half* __restrict__ Kh,
    const __half* __restrict__ VTh, __half* __restrict__ O) {
    extern __shared__ __half sma[];
    __half* Qs = sma;                          // [128][136]
    __half* Kb = Qs + 128 * ATT_QP;            // 2 x [64][136]
    __half* Vb = Kb + 2 * 64 * ATT_KP;         // 2 x [128][72]

    int h  = blockIdx.y;
    int it = gridDim.x - 1 - blockIdx.x;       // big tiles first
    int i0 = it * 128;
    int hk = h >> 1;                           // NREP = 2
    int tid = threadIdx.x, wid = tid >> 5, lane = tid & 31;
    int lr = lane >> 2, lc = lane & 3;
    int wrow = wid * 16;

    // K/V stage loader (cp.async)
    auto issue_att = [&](int kt, int s) {
        int j0 = kt * 64;
        __half* Kd = Kb + s * 64 * ATT_KP;
        __half* Vd = Vb + s * 128 * ATT_VP;
        #pragma unroll
        for (int i = 0; i < 4; i++) {
            int cid = tid + i * 256;
            int r = cid >> 4, ch = cid & 15;
            const __half* g = Kh + ((size_t)(j0 + r) * HKV + hk) * DD + ch * 8;
            uint32_t dst = (uint32_t)__cvta_generic_to_shared(&Kd[r * ATT_KP + ch * 8]);
            CP_ASYNC16(dst, g);
        }
        #pragma unroll
        for (int i = 0; i < 4; i++) {
            int cid = tid + i * 256;
            int d = cid >> 3, ch = cid & 7;
            const __half* g = VTh + ((size_t)hk * DD + d) * TT + j0 + ch * 8;
            uint32_t dst = (uint32_t)__cvta_generic_to_shared(&Vd[d * ATT_VP + ch * 8]);
            CP_ASYNC16(dst, g);
        }
        asm volatile("cp.async.commit_group;\n");
    };

    for (int idx = tid; idx < 2048; idx += 256) {
        int r = idx >> 4, ch = idx & 15;
        *(uint4*)&Qs[r * ATT_QP + ch * 8] =
            *(const uint4*)(Qh + ((size_t)(i0 + r) * HH + h) * DD + ch * 8);
    }

    float m_r0 = -1e30f, m_r1 = -1e30f, l_r0 = 0.f, l_r1 = 0.f;
    float oacc[16][4] = {};

    int nk = 2 * it + 2;
    issue_att(0, 0);

    for (int kt = 0; kt < nk; kt++) {
        asm volatile("cp.async.wait_group 0;\n");
        __syncthreads();                       // tile kt resident; buf kt-1 free
        if (kt + 1 < nk) issue_att(kt + 1, (kt + 1) & 1);
        const __half* Ks  = Kb + (kt & 1) * 64 * ATT_KP;
        const __half* VTs = Vb + (kt & 1) * 128 * ATT_VP;
        int j0 = kt * 64;

        float sacc[8][4] = {};
        #pragma unroll
        for (int ks = 0; ks < 8; ks++) {
            int k0 = ks * 16;
            uint32_t a[4];
            const __half* ap = Qs + (wrow + lr) * ATT_QP + k0 + 2 * lc;
            a[0] = *(const uint32_t*)(ap);
            a[1] = *(const uint32_t*)(ap + 8 * ATT_QP);
            a[2] = *(const uint32_t*)(ap + 8);
            a[3] = *(const uint32_t*)(ap + 8 * ATT_QP + 8);
            #pragma unroll
            for (int nf = 0; nf < 8; nf++) {
                uint32_t b[2];
                const __half* bp = Ks + (nf * 8 + lr) * ATT_KP + k0 + 2 * lc;
                b[0] = *(const uint32_t*)(bp);
                b[1] = *(const uint32_t*)(bp + 8);
                MMA_F16(sacc[nf], a, b);
            }
        }
        if (kt >= nk - 2) {
            int r0g = i0 + wrow + lr;
            #pragma unroll
            for (int nf = 0; nf < 8; nf++) {
                int col = j0 + nf * 8 + 2 * lc;
                if (col     > r0g)     sacc[nf][0] = -1e30f;
                if (col + 1 > r0g)     sacc[nf][1] = -1e30f;
                if (col     > r0g + 8) sacc[nf][2] = -1e30f;
                if (col + 1 > r0g + 8) sacc[nf][3] = -1e30f;
            }
        }
        float mx0 = m_r0, mx1 = m_r1;
        #pragma unroll
        for (int nf = 0; nf < 8; nf++) {
            mx0 = fmaxf(mx0, fmaxf(sacc[nf][0], sacc[nf][1]));
            mx1 = fmaxf(mx1, fmaxf(sacc[nf][2], sacc[nf][3]));
        }
        mx0 = fmaxf(mx0, __shfl_xor_sync(0xffffffffu, mx0, 1));
        mx0 = fmaxf(mx0, __shfl_xor_sync(0xffffffffu, mx0, 2));
        mx1 = fmaxf(mx1, __shfl_xor_sync(0xffffffffu, mx1, 1));
        mx1 = fmaxf(mx1, __shfl_xor_sync(0xffffffffu, mx1, 2));
        float al0 = __expf(m_r0 - mx0), al1 = __expf(m_r1 - mx1);
        m_r0 = mx0; m_r1 = mx1;
        float s0 = 0.f, s1 = 0.f;
        uint32_t pf[8][2];
        #pragma unroll
        for (int nf = 0; nf < 8; nf++) {
            float p0 = __expf(sacc[nf][0] - mx0);
            float p1 = __expf(sacc[nf][1] - mx0);
            float p2 = __expf(sacc[nf][2] - mx1);
            float p3 = __expf(sacc[nf][3] - mx1);
            s0 += p0 + p1; s1 += p2 + p3;
            __half2 h01 = __floats2half2_rn(p0, p1);
            __half2 h23 = __floats2half2_rn(p2, p3);
            pf[nf][0] = *(uint32_t*)&h01;
            pf[nf][1] = *(uint32_t*)&h23;
        }
        s0 += __shfl_xor_sync(0xffffffffu, s0, 1);
        s0 += __shfl_xor_sync(0xffffffffu, s0, 2);
        s1 += __shfl_xor_sync(0xffffffffu, s1, 1);
        s1 += __shfl_xor_sync(0xffffffffu, s1, 2);
        l_r0 = l_r0 * al0 + s0;
        l_r1 = l_r1 * al1 + s1;
        #pragma unroll
        for (int nf = 0; nf < 16; nf++) {
            oacc[nf][0] *= al0; oacc[nf][1] *= al0;
            oacc[nf][2] *= al1; oacc[nf][3] *= al1;
        }
        #pragma unroll
        for (int ks = 0; ks < 4; ks++) {
            uint32_t a[4] = { pf[2 * ks][0], pf[2 * ks][1],
                              pf[2 * ks + 1][0], pf[2 * ks + 1][1] };
            #pragma unroll
            for (int nf = 0; nf < 16; nf++) {
                uint32_t b[2];
                const __half* bp = VTs + (nf * 8 + lr) * ATT_VP + 16 * ks + 2 * lc;
                b[0] = *(const uint32_t*)(bp);
                b[1] = *(const uint32_t*)(bp + 8);
                MMA_F16(oacc[nf], a, b);
            }
        }
    }
    float inv0 = 1.f / l_r0, inv1 = 1.f / l_r1;
    #pragma unroll
    for (int nf = 0; nf < 16; nf++) {
        int d = nf * 8 + 2 * lc;
        __half2 o0 = __floats2half2_rn(oacc[nf][0] * inv0, oacc[nf][1] * inv0);
        __half2 o1 = __floats2half2_rn(oacc[nf][2] * inv1, oacc[nf][3] * inv1);
        *(uint32_t*)(O + ((size_t)(i0 + wrow + lr) * HH + h) * DD + d) = *(uint32_t*)&o0;
        *(uint32_t*)(O + ((size_t)(i0 + wrow + lr + 8) * HH + h) * DD + d) = *(uint32_t*)&o1;
    }
}

// ---------------- launch ----------------
extern "C" void kernel_launch(void* const* d_in, const int* in_sizes, int n_in,
                              void* d_out, int out_size) {
    const float* hc    = (const float*)d_in[0];
    const float* cosT  = (const float*)d_in[1];
    const float* sinT  = (const float*)d_in[2];
    const float* wq    = (const float*)d_in[5];
    const float* wk    = (const float*)d_in[6];
    const float* wv    = (const float*)d_in[7];
    const float* wo    = (const float*)d_in[8];
    const float* wgu   = (const float*)d_in[9];
    const float* wd    = (const float*)d_in[10];
    const float* ilnw  = (const float*)d_in[11];
    const float* plnw  = (const float*)d_in[12];
    const float* qnw   = (const float*)d_in[13];
    const float* knw   = (const float*)d_in[14];
    float* out = (float*)d_out;

    float *px, *phid;
    __half *phh, *patth, *ph2h, *pacth, *pqh, *pkh, *pvh, *pvth;
    __half *pwqkv, *pwo, *pwgu, *pwd;
    cudaGetSymbolAddress((void**)&px,    g_x);
    cudaGetSymbolAddress((void**)&phid,  g_hid);
    cudaGetSymbolAddress((void**)&phh,   g_h_h);
    cudaGetSymbolAddress((void**)&patth, g_att_h);
    cudaGetSymbolAddress((void**)&ph2h,  g_h2_h);
    cudaGetSymbolAddress((void**)&pacth, g_act_h);
    cudaGetSymbolAddress((void**)&pqh,   g_q_h);
    cudaGetSymbolAddress((void**)&pkh,   g_k_h);
    cudaGetSymbolAddress((void**)&pvh,   g_v_h);
    cudaGetSymbolAddress((void**)&pvth,  g_vt_h);
    cudaGetSymbolAddress((void**)&pwqkv, g_wqkv_h);
    cudaGetSymbolAddress((void**)&pwo,   g_wo_h);
    cudaGetSymbolAddress((void**)&pwgu,  g_wgu_h);
    cudaGetSymbolAddress((void**)&pwd,   g_wd_h);

    cudaFuncSetAttribute(flash_attn_h, cudaFuncAttributeMaxDynamicSharedMemorySize, ATT_SMEM);
    cudaFuncSetAttribute((const void*)gemm_f16<1, 128, 2>, cudaFuncAttributeMaxDynamicSharedMemorySize, SMEM_G(128));
    cudaFuncSetAttribute((const void*)gemm_f16<0, 128, 2>, cudaFuncAttributeMaxDynamicSharedMemorySize, SMEM_G(128));
    cudaFuncSetAttribute((const void*)gemm_f16<2, 256, 1>, cudaFuncAttributeMaxDynamicSharedMemorySize, SMEM_G(256));
    cudaFuncSetAttribute((const void*)gemm_f16<3, 256, 1>, cudaFuncAttributeMaxDynamicSharedMemorySize, SMEM_G(256));

    dim3 tb(32, 8);

    // 0. convert weights to fp16 (qkv fused into one launch; wgu interleaved)
    cvt_f16_qkv<<<4096, 256>>>((const float4*)wq, (const float4*)wk, (const float4*)wv,
                               (uint4*)pwqkv);
    cvt_f16<<<(2048 * 2048 / 8) / 256, 256>>>((const float4*)wo, (uint4*)pwo, 2048 * 2048 / 8);
    cvt_f16_gu<<<(16384 * 256) / 256, 256>>>((const float4*)wgu, (uint4*)pwgu);
    cvt_f16<<<(2048 * 8192 / 8) / 256, 256>>>((const float4*)wd, (uint4*)pwd, 2048 * 8192 / 8);

    // 1. x = hidden_conv^T
    transpose_k<<<dim3(TT / 32, HID / 32), tb>>>(hc, px, HID, TT);
    // 2. h = rms(x) * input_ln_w -> fp16
    rms_rows_h<<<TT, 256>>>(px, ilnw, phh, HID);
    // 3. fused QKV projection -> fp16 q/k/v directly (BN=128, occ 2)
    gemm_f16<1, 128, 2><<<dim3(32, 16), 256, SMEM_G(128)>>>(
        phh, pwqkv, nullptr, nullptr, pqh, pkh, pvh, 4096, HID);
    // 4. q/k head-RMS + rope in place (q pre-scaled); V transpose
    qk_rms_rope_h2<<<dim3(HH,  TT), 128>>>(pqh, qnw, cosT, sinT, SCALEF);
    qk_rms_rope_h2<<<dim3(HKV, TT), 128>>>(pkh, knw, cosT, sinT, 1.0f);
    v_trans_h2<<<dim3(TT / 32, DD / 32, HKV), tb>>>(pvh, pvth);
    // 5. tensor-core flash attention (cp.async K/V pipeline) -> fp16 att
    flash_attn_h<<<dim3(TT / 128, HH), 256, ATT_SMEM>>>(pqh, pkh, pvth, patth);
    // 6. hidden = x + att @ wo^T (BN=128, occ 2)
    gemm_f16<0, 128, 2><<<dim3(16, 16), 256, SMEM_G(128)>>>(
        patth, pwo, px, phid, nullptr, nullptr, nullptr, HID, HH * DD);
    // 7. h2 = rms(hidden) * post_ln_w -> fp16
    rms_rows_h<<<TT, 256>>>(phid, plnw, ph2h, HID);
    // 8. gate_up with fused silu -> fp16 act (BN=256, warp 64x64)
    gemm_f16<2, 256, 1><<<dim3(64, 16), 256, SMEM_G(256)>>>(
        ph2h, pwgu, nullptr, nullptr, pacth, nullptr, nullptr, 2 * II, HID);
    // 9. out = (hidden + act @ w_down^T)^T  (BN=256, residual + staged transposed store)
    gemm_f16<3, 256, 1><<<dim3(8, 16), 256, SMEM_G(256)>>>(
        pacth, pwd, phid, out, nullptr, nullptr, nullptr, HID, II);
}

// round 17
// speedup vs baseline: 1.0519x; 1.0519x over previous
#include <cuda_runtime.h>
#include <cuda_bf16.h>
#include <cuda_fp16.h>
#include <cstdint>
#include <math.h>

// ---------------- problem constants ----------------
#define HH   16        // H
#define HKV  8
#define DD   128       // D
#define TT   2048      // T
#define HID  2048
#define II   8192      // I
#define NREP 2
#define EPSF 1e-6f
#define SCALEF 0.08838834764831845f   // 1/sqrt(128)

// ---------------- scratch (device globals, no allocs) ----------------
__device__ float g_x  [TT * HID];
__device__ float g_hid[TT * HID];
// fp16 activation buffers
__device__ __align__(16) __half g_h_h  [TT * HID];
__device__ __align__(16) __half g_att_h[TT * HH * DD];
__device__ __align__(16) __half g_h2_h [TT * HID];
__device__ __align__(16) __half g_act_h[TT * II];
__device__ __align__(16) __half g_q_h  [TT * HH * DD];
__device__ __align__(16) __half g_k_h  [TT * HKV * DD];
__device__ __align__(16) __half g_v_h  [TT * HKV * DD];
__device__ __align__(16) __half g_vt_h [HKV * DD * TT];  // [hk][d][t]
// fp16 weights (converted every replay)
__device__ __align__(16) __half g_wqkv_h[4096 * HID];
__device__ __align__(16) __half g_wgu_h [2 * II * HID];  // gate/up row-interleaved
__device__ __align__(16) __half g_wo_h  [HID * HH * DD];
__device__ __align__(16) __half g_wd_h  [HID * II];

// ---------------- fp32 -> fp16 conversion (8 floats / thread) ----------------
__device__ __forceinline__ uint4 cvt8(float4 a, float4 b) {
    __half2 h0 = __floats2half2_rn(a.x, a.y);
    __half2 h1 = __floats2half2_rn(a.z, a.w);
    __half2 h2 = __floats2half2_rn(b.x, b.y);
    __half2 h3 = __floats2half2_rn(b.z, b.w);
    return make_uint4(*(uint32_t*)&h0, *(uint32_t*)&h1,
                      *(uint32_t*)&h2, *(uint32_t*)&h3);
}

__global__ void cvt_f16(const float4* __restrict__ src, uint4* __restrict__ dst, int n8) {
    int i = blockIdx.x * blockDim.x + threadIdx.x;
    if (i < n8) {
        float4 a = src[2 * i], b = src[2 * i + 1];
        dst[i] = cvt8(a, b);
    }
}

// fused wq/wk/wv conversion (one launch)
__global__ void cvt_f16_qkv(const float4* __restrict__ wq, const float4* __restrict__ wk,
                            const float4* __restrict__ wv, uint4* __restrict__ dst) {
    int i = blockIdx.x * blockDim.x + threadIdx.x;   // 1048576 threads
    const float4* s;
    uint4* d;
    if (i < 524288)      { s = wq + 2 * i;                     d = dst + i; }
    else if (i < 786432) { int j = i - 524288; s = wk + 2 * j; d = dst + 524288 + j; }
    else                 { int j = i - 786432; s = wv + 2 * j; d = dst + 786432 + j; }
    float4 a = s[0], b = s[1];
    d[0] = cvt8(a, b);
}

// wgu conversion with gate/up row interleave: dst row 2j = gate_j, 2j+1 = up_j.
__global__ void cvt_f16_gu(const float4* __restrict__ src, uint4* __restrict__ dst) {
    int i = blockIdx.x * blockDim.x + threadIdx.x;   // over 16384*256
    int row = i >> 8, chunk = i & 255;
    int drow = (row < II) ? (row << 1) : (((row - II) << 1) | 1);
    float4 a = src[2 * i], b = src[2 * i + 1];
    dst[drow * 256 + chunk] = cvt8(a, b);
}

// ---------------- transpose: src[R][C] -> dst[C][R] (fp32) ----------------
__global__ void transpose_k(const float* __restrict__ src, float* __restrict__ dst,
                            int R, int C) {
    __shared__ float tile[32][33];
    int r0 = blockIdx.y * 32, c0 = blockIdx.x * 32;
    int tx = threadIdx.x, ty = threadIdx.y;
    #pragma unroll
    for (int i = ty; i < 32; i += 8)
        tile[i][tx] = src[(size_t)(r0 + i) * C + c0 + tx];
    __syncthreads();
    #pragma unroll
    for (int i = ty; i < 32; i += 8)
        dst[(size_t)(c0 + i) * R + r0 + tx] = tile[tx][i];
}

// ---------------- V transpose: [T][HKV][D] f16 -> [hk][d][t] f16 -----
__global__ void v_trans_h2(const __half* __restrict__ V, __half* __restrict__ VT) {
    __shared__ __half tile[32][33];
    int t0 = blockIdx.x * 32, d0 = blockIdx.y * 32, hk = blockIdx.z;
    int tx = threadIdx.x, ty = threadIdx.y;
    #pragma unroll
    for (int i = ty; i < 32; i += 8)
        tile[i][tx] = V[((size_t)(t0 + i) * HKV + hk) * DD + d0 + tx];
    __syncthreads();
    #pragma unroll
    for (int i = ty; i < 32; i += 8)
        VT[((size_t)hk * DD + d0 + i) * TT + t0 + tx] = tile[tx][i];
}

// ---------------- row RMS norm, fp16 output ----------------
__global__ void rms_rows_h(const float* __restrict__ X, const float* __restrict__ w,
                           __half* __restrict__ Y, int C) {
    int t = blockIdx.x;
    const float4* x4 = (const float4*)(X + (size_t)t * C);
    const float4* w4 = (const float4*)w;
    __half2*      y2 = (__half2*)(Y + (size_t)t * C);
    int n4 = C >> 2;
    float4 v[4];
    float ss = 0.f;
    int cnt = 0;
    for (int i = threadIdx.x; i < n4; i += 256) {
        float4 a = x4[i];
        v[cnt++] = a;
        ss += a.x * a.x + a.y * a.y + a.z * a.z + a.w * a.w;
    }
    #pragma unroll
    for (int o = 16; o; o >>= 1) ss += __shfl_xor_sync(0xffffffffu, ss, o);
    __shared__ float warpsum[8];
    if ((threadIdx.x & 31) == 0) warpsum[threadIdx.x >> 5] = ss;
    __syncthreads();
    ss = 0.f;
    #pragma unroll
    for (int i = 0; i < 8; i++) ss += warpsum[i];
    float r = rsqrtf(ss / (float)C + EPSF);
    cnt = 0;
    for (int i = threadIdx.x; i < n4; i += 256) {
        float4 a = v[cnt++];
        float4 ww = w4[i];
        y2[2 * i]     = __floats2half2_rn(a.x * r * ww.x, a.y * r * ww.y);
        y2[2 * i + 1] = __floats2half2_rn(a.z * r * ww.z, a.w * r * ww.w);
    }
}

// ---------------- per-head RMS + RoPE, fp16 in-place ----------------
__global__ void qk_rms_rope_h2(__half* __restrict__ buf, const float* __restrict__ w,
                               const float* __restrict__ cosT, const float* __restrict__ sinT,
                               float scale) {
    int h = blockIdx.x, t = blockIdx.y, nh = gridDim.x;
    __half* row = buf + ((size_t)t * nh + h) * DD;
    int d = threadIdx.x;
    float v = __half2float(row[d]);
    float ss = v * v;
    #pragma unroll
    for (int o = 16; o; o >>= 1) ss += __shfl_xor_sync(0xffffffffu, ss, o);
    __shared__ float wsum[4];
    if ((d & 31) == 0) wsum[d >> 5] = ss;
    __syncthreads();
    ss = wsum[0] + wsum[1] + wsum[2] + wsum[3];
    float r = rsqrtf(ss / 128.f + EPSF);
    float qn = v * r * w[d];
    __shared__ float sh[128];
    sh[d] = qn;
    __syncthreads();
    float rot = (d < 64) ? -sh[d + 64] : sh[d - 64];
    float val = (qn * cosT[(size_t)t * DD + d] + rot * sinT[(size_t)t * DD + d]) * scale;
    row[d] = __float2half(val);
}

#define MMA_F16(d, a, b)                                                      \
    asm volatile("mma.sync.aligned.m16n8k16.row.col.f32.f16.f16.f32 "         \
                 "{%0,%1,%2,%3}, {%4,%5,%6,%7}, {%8,%9}, {%0,%1,%2,%3};"      \
                 : "+f"(d[0]), "+f"(d[1]), "+f"(d[2]), "+f"(d[3])             \
                 : "r"(a[0]), "r"(a[1]), "r"(a[2]), "r"(a[3]),                \
                   "r"(b[0]), "r"(b[1]))

#define LDSM_X4(r0, r1, r2, r3, addr)                                         \
    asm volatile("ldmatrix.sync.aligned.m8n8.x4.shared.b16 {%0,%1,%2,%3}, [%4];" \
                 : "=r"(r0), "=r"(r1), "=r"(r2), "=r"(r3) : "r"(addr))

#define CP_ASYNC16(dst, src)                                                  \
    asm volatile("cp.async.cg.shared.global [%0], [%1], 16;\n"                \
                 :: "r"(dst), "l"(src))

// ---------------- fp16 tensor-core GEMM, cp.async 3-stage, BK=64, ldmatrix ---
// C[M,N] = A[M,K] * B[N,K]^T.  BN=128 (warp 64x32), 2 CTAs/SM.
// MODE 0: +Res, fp32 out.  MODE 1: QKV routing, fp16 out.
// MODE 2: gate/up interleaved -> fused silu, fp16 out [M][N/2].
// MODE 3: +Res, fp32 out TRANSPOSED via smem staging ([N][T] layout).
#define HPITCH 72    // halfs per smem row (144 B): ldmatrix 8-row phase conflict-free
#define SMEM_F16 (3 * (128 + 128) * HPITCH * 2)   // 110592 B

template<int MODE>
__global__ __launch_bounds__(256, 2) void gemm_f16(
    const __half* __restrict__ A, const __half* __restrict__ B,
    const float* __restrict__ Res, float* __restrict__ C,
    __half* __restrict__ H0, __half* __restrict__ H1, __half* __restrict__ H2,
    int N, int K) {
    constexpr int BM = 128, BN = 128;
    extern __shared__ __half shm[];
    __half* SA = shm;                     // [3][BM][HPITCH]
    __half* SB = shm + 3 * BM * HPITCH;   // [3][BN][HPITCH]

    const int bm = blockIdx.y * BM;
    const int bn = blockIdx.x * BN;
    const int tid = threadIdx.x;
    const int wid = tid >> 5, lane = tid & 31;
    const int wm = wid & 1, wn = wid >> 1;
    const int lr = lane >> 2, lc = lane & 3;
    const int nkt = K >> 6;

    // ldmatrix lane-address components
    const int amat = lane >> 3;
    const int arow = ((amat & 1) << 3) + (lane & 7);
    const int acol = (amat >> 1) << 3;
    const int brow = ((amat >> 1) << 3) + (lane & 7);
    const int bcol = (amat & 1) << 3;
    const uint32_t sa0 = (uint32_t)__cvta_generic_to_shared(SA);
    const uint32_t sb0 = (uint32_t)__cvta_generic_to_shared(SB);
    const uint32_t a_off = sa0 + ((wm * 64 + arow) * HPITCH + acol) * 2;
    const uint32_t b_off = sb0 + ((wn * 32 + brow) * HPITCH + bcol) * 2;

    auto issue = [&](int kt, int s) {
        int k0 = kt << 6;
        #pragma unroll
        for (int i = 0; i < 4; i++) {
            int cid = tid + i * 256;
            int r = cid >> 3, ch = cid & 7;          // 8 x 16B chunks per 128B row
            const __half* g = A + (size_t)(bm + r) * K + k0 + ch * 8;
            uint32_t dst = (uint32_t)__cvta_generic_to_shared(
                &SA[(s * BM + r) * HPITCH + ch * 8]);
            CP_ASYNC16(dst, g);
        }
        #pragma unroll
        for (int i = 0; i < 4; i++) {
            int cid = tid + i * 256;
            int r = cid >> 3, ch = cid & 7;
            const __half* g = B + (size_t)(bn + r) * K + k0 + ch * 8;
            uint32_t dst = (uint32_t)__cvta_generic_to_shared(
                &SB[(s * BN + r) * HPITCH + ch * 8]);
            CP_ASYNC16(dst, g);
        }
        asm volatile("cp.async.commit_group;\n");
    };

    float acc[4][4][4] = {};

    issue(0, 0);
    issue(1, 1);

    for (int kt = 0; kt < nkt; kt++) {
        int s = kt % 3;
        if (kt == nkt - 1) { asm volatile("cp.async.wait_group 0;\n"); }
        else               { asm volatile("cp.async.wait_group 1;\n"); }
        __syncthreads();
        if (kt + 2 < nkt) issue(kt + 2, (kt + 2) % 3);

        uint32_t abase = a_off + s * (BM * HPITCH * 2);
        uint32_t bbase = b_off + s * (BN * HPITCH * 2);
        #pragma unroll
        for (int ks = 0; ks < 64; ks += 16) {
            uint32_t af[4][4], bf[4][2];
            #pragma unroll
            for (int mf = 0; mf < 4; mf++)
                LDSM_X4(af[mf][0], af[mf][1], af[mf][2], af[mf][3],
                        abase + (mf * 16 * HPITCH + ks) * 2);
            #pragma unroll
            for (int t = 0; t < 2; t++)
                LDSM_X4(bf[2 * t][0], bf[2 * t][1], bf[2 * t + 1][0], bf[2 * t + 1][1],
                        bbase + (t * 16 * HPITCH + ks) * 2);
            #pragma unroll
            for (int mf = 0; mf < 4; mf++)
                #pragma unroll
                for (int nf = 0; nf < 4; nf++)
                    MMA_F16(acc[mf][nf], af[mf], bf[nf]);
        }
    }

    if (MODE == 1) {
        // fp16 QKV routing
        __half* Cb;
        int Nloc, cl0;
        if (bn < 2048)      { Cb = H0; Nloc = 2048; cl0 = bn; }
        else if (bn < 3072) { Cb = H1; Nloc = 1024; cl0 = bn - 2048; }
        else                { Cb = H2; Nloc = 1024; cl0 = bn - 3072; }
        #pragma unroll
        for (int mf = 0; mf < 4; mf++) {
            #pragma unroll
            for (int nf = 0; nf < 4; nf++) {
                int rg = bm + wm * 64 + mf * 16 + lr;
                int cg = cl0 + wn * 32 + nf * 8 + 2 * lc;
                __half2 v0 = __floats2half2_rn(acc[mf][nf][0], acc[mf][nf][1]);
                __half2 v1 = __floats2half2_rn(acc[mf][nf][2], acc[mf][nf][3]);
                *(__half2*)(Cb + (size_t)rg * Nloc + cg) = v0;
                *(__half2*)(Cb + (size_t)(rg + 8) * Nloc + cg) = v1;
            }
        }
        return;
    }
    if (MODE == 2) {
        #pragma unroll
        for (int mf = 0; mf < 4; mf++) {
            #pragma unroll
            for (int nf = 0; nf < 4; nf++) {
                int rg = bm + wm * 64 + mf * 16 + lr;
                int j = ((bn + wn * 32 + nf * 8) >> 1) + lc;
                float g0 = acc[mf][nf][0], u0 = acc[mf][nf][1];
                float g1 = acc[mf][nf][2], u1 = acc[mf][nf][3];
                H0[(size_t)rg * (N / 2) + j] =
                    __float2half(g0 / (1.f + __expf(-g0)) * u0);
                H0[(size_t)(rg + 8) * (N / 2) + j] =
                    __float2half(g1 / (1.f + __expf(-g1)) * u1);
            }
        }
        return;
    }
    if (MODE == 3) {
        // residual add, stage through smem (pitch 132), coalesced transposed store
        __syncthreads();
        float* sf = (float*)shm;          // [128 cols][132] = 67584 B < SMEM_F16
        #pragma unroll
        for (int mf = 0; mf < 4; mf++) {
            #pragma unroll
            for (int nf = 0; nf < 4; nf++) {
                int rl = wm * 64 + mf * 16 + lr;
                int cl = wn * 32 + nf * 8 + 2 * lc;
                int rg = bm + rl;
                float2 r0 = *(const float2*)(Res + (size_t)rg * N + bn + cl);
                float2 r1 = *(const float2*)(Res + (size_t)(rg + 8) * N + bn + cl);
                sf[cl * 132 + rl]           = acc[mf][nf][0] + r0.x;
                sf[(cl + 1) * 132 + rl]     = acc[mf][nf][1] + r0.y;
                sf[cl * 132 + rl + 8]       = acc[mf][nf][2] + r1.x;
                sf[(cl + 1) * 132 + rl + 8] = acc[mf][nf][3] + r1.y;
            }
        }
        __syncthreads();
        #pragma unroll
        for (int i = 0; i < 16; i++) {
            int cl = wid * 16 + i;
            #pragma unroll
            for (int j = 0; j < 4; j++)
                C[(size_t)(bn + cl) * TT + bm + lane + 32 * j] =
                    sf[cl * 132 + lane + 32 * j];
        }
        return;
    }
    // MODE 0
    #pragma unroll
    for (int mf = 0; mf < 4; mf++) {
        #pragma unroll
        for (int nf = 0; nf < 4; nf++) {
            int rg = bm + wm * 64 + mf * 16 + lr;
            int cg = bn + wn * 32 + nf * 8 + 2 * lc;
            float2 v0 = make_float2(acc[mf][nf][0], acc[mf][nf][1]);
            float2 v1 = make_float2(acc[mf][nf][2], acc[mf][nf][3]);
            if (Res) {
                float2 r0 = *(const float2*)(Res + (size_t)rg * N + cg);
                float2 r1 = *(const float2*)(Res + (size_t)(rg + 8) * N + cg);
                v0.x += r0.x; v0.y += r0.y;
                v1.x += r1.x; v1.y += r1.y;
            }
            *(float2*)(C + (size_t)rg * N + cg) = v0;
            *(float2*)(C + (size_t)(rg + 8) * N + cg) = v1;
        }
    }
}

// ---------------- tensor-core flash attention, cp.async double-buffered K/V --
#define ATT_QP 136
#define ATT_KP 136
#define ATT_VP 72
#define ATT_SMEM ((128 * ATT_QP + 2 * (64 * ATT_KP + 128 * ATT_VP)) * 2)  // 106496 B

__global__ __launch_bounds__(256, 1) void flash_attn_h(
    const __half* __restrict__ Qh, const __half* __restrict__ Kh,
    const __half* __restrict__ VTh, __half* __restrict__ O) {
    extern __shared__ __half sma[];
    __half* Qs = sma;                          // [128][136]
    __half* Kb = Qs + 128 * ATT_QP;            // 2 x [64][136]
    __half* Vb = Kb + 2 * 64 * ATT_KP;         // 2 x [128][72]

    int h  = blockIdx.y;
    int it = gridDim.x - 1 - blockIdx.x;       // big tiles first
    int i0 = it * 128;
    int hk = h >> 1;                           // NREP = 2
    int tid = threadIdx.x, wid = tid >> 5, lane = tid & 31;
    int lr = lane >> 2, lc = lane & 3;
    int wrow = wid * 16;

    // K/V stage loader (cp.async)
    auto issue_att = [&](int kt, int s) {
        int j0 = kt * 64;
        __half* Kd = Kb + s * 64 * ATT_KP;
        __half* Vd = Vb + s * 128 * ATT_VP;
        #pragma unroll
        for (int i = 0; i < 4; i++) {
            int cid = tid + i * 256;
            int r = cid >> 4, ch = cid & 15;
            const __half* g = Kh + ((size_t)(j0 + r) * HKV + hk) * DD + ch * 8;
            uint32_t dst = (uint32_t)__cvta_generic_to_shared(&Kd[r * ATT_KP + ch * 8]);
            CP_ASYNC16(dst, g);
        }
        #pragma unroll
        for (int i = 0; i < 4; i++) {
            int cid = tid + i * 256;
            int d = cid >> 3, ch = cid & 7;
            const __half* g = VTh + ((size_t)hk * DD + d) * TT + j0 + ch * 8;
            uint32_t dst = (uint32_t)__cvta_generic_to_shared(&Vd[d * ATT_VP + ch * 8]);
            CP_ASYNC16(dst, g);
        }
        asm volatile("cp.async.commit_group;\n");
    };

    for (int idx = tid; idx < 2048; idx += 256) {
        int r = idx >> 4, ch = idx & 15;
        *(uint4*)&Qs[r * ATT_QP + ch * 8] =
            *(const uint4*)(Qh + ((size_t)(i0 + r) * HH + h) * DD + ch * 8);
    }

    float m_r0 = -1e30f, m_r1 = -1e30f, l_r0 = 0.f, l_r1 = 0.f;
    float oacc[16][4] = {};

    int nk = 2 * it + 2;
    issue_att(0, 0);

    for (int kt = 0; kt < nk; kt++) {
        asm volatile("cp.async.wait_group 0;\n");
        __syncthreads();                       // tile kt resident; buf kt-1 free
        if (kt + 1 < nk) issue_att(kt + 1, (kt + 1) & 1);
        const __half* Ks  = Kb + (kt & 1) * 64 * ATT_KP;
        const __half* VTs = Vb + (kt & 1) * 128 * ATT_VP;
        int j0 = kt * 64;

        float sacc[8][4] = {};
        #pragma unroll
        for (int ks = 0; ks < 8; ks++) {
            int k0 = ks * 16;
            uint32_t a[4];
            const __half* ap = Qs + (wrow + lr) * ATT_QP + k0 + 2 * lc;
            a[0] = *(const uint32_t*)(ap);
            a[1] = *(const uint32_t*)(ap + 8 * ATT_QP);
            a[2] = *(const uint32_t*)(ap + 8);
            a[3] = *(const uint32_t*)(ap + 8 * ATT_QP + 8);
            #pragma unroll
            for (int nf = 0; nf < 8; nf++) {
                uint32_t b[2];
                const __half* bp = Ks + (nf * 8 + lr) * ATT_KP + k0 + 2 * lc;
                b[0] = *(const uint32_t*)(bp);
                b[1] = *(const uint32_t*)(bp + 8);
                MMA_F16(sacc[nf], a, b);
            }
        }
        if (kt >= nk - 2) {
            int r0g = i0 + wrow + lr;
            #pragma unroll
            for (int nf = 0; nf < 8; nf++) {
                int col = j0 + nf * 8 + 2 * lc;
                if (col     > r0g)     sacc[nf][0] = -1e30f;
                if (col + 1 > r0g)     sacc[nf][1] = -1e30f;
                if (col     > r0g + 8) sacc[nf][2] = -1e30f;
                if (col + 1 > r0g + 8) sacc[nf][3] = -1e30f;
            }
        }
        float mx0 = m_r0, mx1 = m_r1;
        #pragma unroll
        for (int nf = 0; nf < 8; nf++) {
            mx0 = fmaxf(mx0, fmaxf(sacc[nf][0], sacc[nf][1]));
            mx1 = fmaxf(mx1, fmaxf(sacc[nf][2], sacc[nf][3]));
        }
        mx0 = fmaxf(mx0, __shfl_xor_sync(0xffffffffu, mx0, 1));
        mx0 = fmaxf(mx0, __shfl_xor_sync(0xffffffffu, mx0, 2));
        mx1 = fmaxf(mx1, __shfl_xor_sync(0xffffffffu, mx1, 1));
        mx1 = fmaxf(mx1, __shfl_xor_sync(0xffffffffu, mx1, 2));
        float al0 = __expf(m_r0 - mx0), al1 = __expf(m_r1 - mx1);
        m_r0 = mx0; m_r1 = mx1;
        float s0 = 0.f, s1 = 0.f;
        uint32_t pf[8][2];
        #pragma unroll
        for (int nf = 0; nf < 8; nf++) {
            float p0 = __expf(sacc[nf][0] - mx0);
            float p1 = __expf(sacc[nf][1] - mx0);
            float p2 = __expf(sacc[nf][2] - mx1);
            float p3 = __expf(sacc[nf][3] - mx1);
            s0 += p0 + p1; s1 += p2 + p3;
            __half2 h01 = __floats2half2_rn(p0, p1);
            __half2 h23 = __floats2half2_rn(p2, p3);
            pf[nf][0] = *(uint32_t*)&h01;
            pf[nf][1] = *(uint32_t*)&h23;
        }
        s0 += __shfl_xor_sync(0xffffffffu, s0, 1);
        s0 += __shfl_xor_sync(0xffffffffu, s0, 2);
        s1 += __shfl_xor_sync(0xffffffffu, s1, 1);
        s1 += __shfl_xor_sync(0xffffffffu, s1, 2);
        l_r0 = l_r0 * al0 + s0;
        l_r1 = l_r1 * al1 + s1;
        #pragma unroll
        for (int nf = 0; nf < 16; nf++) {
            oacc[nf][0] *= al0; oacc[nf][1] *= al0;
            oacc[nf][2] *= al1; oacc[nf][3] *= al1;
        }
        #pragma unroll
        for (int ks = 0; ks < 4; ks++) {
            uint32_t a[4] = { pf[2 * ks][0], pf[2 * ks][1],
                              pf[2 * ks + 1][0], pf[2 * ks + 1][1] };
            #pragma unroll
            for (int nf = 0; nf < 16; nf++) {
                uint32_t b[2];
                const __half* bp = VTs + (nf * 8 + lr) * ATT_VP + 16 * ks + 2 * lc;
                b[0] = *(const uint32_t*)(bp);
                b[1] = *(const uint32_t*)(bp + 8);
                MMA_F16(oacc[nf], a, b);
            }
        }
    }
    float inv0 = 1.f / l_r0, inv1 = 1.f / l_r1;
    #pragma unroll
    for (int nf = 0; nf < 16; nf++) {
        int d = nf * 8 + 2 * lc;
        __half2 o0 = __floats2half2_rn(oacc[nf][0] * inv0, oacc[nf][1] * inv0);
        __half2 o1 = __floats2half2_rn(oacc[nf][2] * inv1, oacc[nf][3] * inv1);
        *(uint32_t*)(O + ((size_t)(i0 + wrow + lr) * HH + h) * DD + d) = *(uint32_t*)&o0;
        *(uint32_t*)(O + ((size_t)(i0 + wrow + lr + 8) * HH + h) * DD + d) = *(uint32_t*)&o1;
    }
}

// ---------------- launch ----------------
extern "C" void kernel_launch(void* const* d_in, const int* in_sizes, int n_in,
                              void* d_out, int out_size) {
    const float* hc    = (const float*)d_in[0];
    const float* cosT  = (const float*)d_in[1];
    const float* sinT  = (const float*)d_in[2];
    const float* wq    = (const float*)d_in[5];
    const float* wk    = (const float*)d_in[6];
    const float* wv    = (const float*)d_in[7];
    const float* wo    = (const float*)d_in[8];
    const float* wgu   = (const float*)d_in[9];
    const float* wd    = (const float*)d_in[10];
    const float* ilnw  = (const float*)d_in[11];
    const float* plnw  = (const float*)d_in[12];
    const float* qnw   = (const float*)d_in[13];
    const float* knw   = (const float*)d_in[14];
    float* out = (float*)d_out;

    float *px, *phid;
    __half *phh, *patth, *ph2h, *pacth, *pqh, *pkh, *pvh, *pvth;
    __half *pwqkv, *pwo, *pwgu, *pwd;
    cudaGetSymbolAddress((void**)&px,    g_x);
    cudaGetSymbolAddress((void**)&phid,  g_hid);
    cudaGetSymbolAddress((void**)&phh,   g_h_h);
    cudaGetSymbolAddress((void**)&patth, g_att_h);
    cudaGetSymbolAddress((void**)&ph2h,  g_h2_h);
    cudaGetSymbolAddress((void**)&pacth, g_act_h);
    cudaGetSymbolAddress((void**)&pqh,   g_q_h);
    cudaGetSymbolAddress((void**)&pkh,   g_k_h);
    cudaGetSymbolAddress((void**)&pvh,   g_v_h);
    cudaGetSymbolAddress((void**)&pvth,  g_vt_h);
    cudaGetSymbolAddress((void**)&pwqkv, g_wqkv_h);
    cudaGetSymbolAddress((void**)&pwo,   g_wo_h);
    cudaGetSymbolAddress((void**)&pwgu,  g_wgu_h);
    cudaGetSymbolAddress((void**)&pwd,   g_wd_h);

    cudaFuncSetAttribute(flash_attn_h, cudaFuncAttributeMaxDynamicSharedMemorySize, ATT_SMEM);
    cudaFuncSetAttribute(gemm_f16<0>, cudaFuncAttributeMaxDynamicSharedMemorySize, SMEM_F16);
    cudaFuncSetAttribute(gemm_f16<1>, cudaFuncAttributeMaxDynamicSharedMemorySize, SMEM_F16);
    cudaFuncSetAttribute(gemm_f16<2>, cudaFuncAttributeMaxDynamicSharedMemorySize, SMEM_F16);
    cudaFuncSetAttribute(gemm_f16<3>, cudaFuncAttributeMaxDynamicSharedMemorySize, SMEM_F16);

    // lazy side-stream + events for cvt overlap (created on first, uncaptured call)
    static cudaStream_t sB = nullptr;
    static cudaEvent_t evFork, evQKV, evWO, evGU, evWD;
    static bool streamsOk = false;
    static bool tried = false;
    if (!tried) {
        tried = true;
        if (cudaStreamCreateWithFlags(&sB, cudaStreamNonBlocking) == cudaSuccess &&
            cudaEventCreateWithFlags(&evFork, cudaEventDisableTiming) == cudaSuccess &&
            cudaEventCreateWithFlags(&evQKV,  cudaEventDisableTiming) == cudaSuccess &&
            cudaEventCreateWithFlags(&evWO,   cudaEventDisableTiming) == cudaSuccess &&
            cudaEventCreateWithFlags(&evGU,   cudaEventDisableTiming) == cudaSuccess &&
            cudaEventCreateWithFlags(&evWD,   cudaEventDisableTiming) == cudaSuccess)
            streamsOk = true;
    }

    dim3 tb(32, 8);

    if (streamsOk) {
        // fork: side stream joins capture via event from the origin (null) stream
        cudaEventRecord(evFork, 0);
        cudaStreamWaitEvent(sB, evFork, 0);
        // weight conversions on side stream, ordered by first use
        cvt_f16_qkv<<<4096, 256, 0, sB>>>((const float4*)wq, (const float4*)wk,
                                          (const float4*)wv, (uint4*)pwqkv);
        cudaEventRecord(evQKV, sB);
        cvt_f16<<<(2048 * 2048 / 8) / 256, 256, 0, sB>>>((const float4*)wo, (uint4*)pwo,
                                                         2048 * 2048 / 8);
        cudaEventRecord(evWO, sB);
        cvt_f16_gu<<<(16384 * 256) / 256, 256, 0, sB>>>((const float4*)wgu, (uint4*)pwgu);
        cudaEventRecord(evGU, sB);
        cvt_f16<<<(2048 * 8192 / 8) / 256, 256, 0, sB>>>((const float4*)wd, (uint4*)pwd,
                                                         2048 * 8192 / 8);
        cudaEventRecord(evWD, sB);
    } else {
        cvt_f16_qkv<<<4096, 256>>>((const float4*)wq, (const float4*)wk,
                                   (const float4*)wv, (uint4*)pwqkv);
        cvt_f16<<<(2048 * 2048 / 8) / 256, 256>>>((const float4*)wo, (uint4*)pwo,
                                                  2048 * 2048 / 8);
        cvt_f16_gu<<<(16384 * 256) / 256, 256>>>((const float4*)wgu, (uint4*)pwgu);
        cvt_f16<<<(2048 * 8192 / 8) / 256, 256>>>((const float4*)wd, (uint4*)pwd,
                                                  2048 * 8192 / 8);
    }

    // 1. x = hidden_conv^T
    transpose_k<<<dim3(TT / 32, HID / 32), tb>>>(hc, px, HID, TT);
    // 2. h = rms(x) * input_ln_w -> fp16
    rms_rows_h<<<TT, 256>>>(px, ilnw, phh, HID);
    // 3. fused QKV projection -> fp16 q/k/v directly
    if (streamsOk) cudaStreamWaitEvent(0, evQKV, 0);
    gemm_f16<1><<<dim3(32, 16), 256, SMEM_F16>>>(
        phh, pwqkv, nullptr, nullptr, pqh, pkh, pvh, 4096, HID);
    // 4. q/k head-RMS + rope in place (q pre-scaled); V transpose
    qk_rms_rope_h2<<<dim3(HH,  TT), 128>>>(pqh, qnw, cosT, sinT, SCALEF);
    qk_rms_rope_h2<<<dim3(HKV, TT), 128>>>(pkh, knw, cosT, sinT, 1.0f);
    v_trans_h2<<<dim3(TT / 32, DD / 32, HKV), tb>>>(pvh, pvth);
    // 5. tensor-core flash attention (cp.async K/V pipeline) -> fp16 att
    flash_attn_h<<<dim3(TT / 128, HH), 256, ATT_SMEM>>>(pqh, pkh, pvth, patth);
    // 6. hidden = x + att @ wo^T
    if (streamsOk) cudaStreamWaitEvent(0, evWO, 0);
    gemm_f16<0><<<dim3(16, 16), 256, SMEM_F16>>>(
        patth, pwo, px, phid, nullptr, nullptr, nullptr, HID, HH * DD);
    // 7. h2 = rms(hidden) * post_ln_w -> fp16
    rms_rows_h<<<TT, 256>>>(phid, plnw, ph2h, HID);
    // 8. gate_up with fused silu -> fp16 act
    if (streamsOk) cudaStreamWaitEvent(0, evGU, 0);
    gemm_f16<2><<<dim3(128, 16), 256, SMEM_F16>>>(
        ph2h, pwgu, nullptr, nullptr, pacth, nullptr, nullptr, 2 * II, HID);
    // 9. out = (hidden + act @ w_down^T)^T  (residual + staged transposed store)
    if (streamsOk) cudaStreamWaitEvent(0, evWD, 0);
    gemm_f16<3><<<dim3(16, 16), 256, SMEM_F16>>>(
        pacth, pwd, phid, out, nullptr, nullptr, nullptr, HID, II);
}